// round 3
// baseline (speedup 1.0000x reference)
#include <cuda_runtime.h>
#include <cuda_bf16.h>
#include <math.h>

// ---------------------------------------------------------------------------
// TransformerBlock: B=8, N=1024, EMBED=768, HEADS=12, HEAD_DIM=64, HIDDEN=3072
// fp32 SIMT baseline: LN kernels + 128x128 tiled SGEMM (fused epilogues) +
// flash-style fused attention (online softmax, no NxN scratch).
// ---------------------------------------------------------------------------

#define B_      8
#define N_      1024
#define EMBED_  768
#define HEADS_  12
#define HD_     64
#define HIDDEN_ 3072
#define TOKENS_ (B_ * N_)          // 8192
#define QKVW_   (3 * EMBED_)       // 2304

// ---- scratch (static device globals: allocation-free) ----
__device__ float g_h   [TOKENS_ * EMBED_];   // ln1 out
__device__ float g_qkv [TOKENS_ * QKVW_];    // qkv projection
__device__ float g_ctx [TOKENS_ * EMBED_];   // attention context
__device__ float g_x1  [TOKENS_ * EMBED_];   // after attn residual
__device__ float g_h2  [TOKENS_ * EMBED_];   // ln2 out
__device__ float g_ffn [TOKENS_ * HIDDEN_];  // fc1/gelu out

// ---------------------------------------------------------------------------
// LayerNorm: one block per row of 768
// ---------------------------------------------------------------------------
__global__ __launch_bounds__(256) void ln_kernel(
    const float* __restrict__ x, const float* __restrict__ g,
    const float* __restrict__ b, float* __restrict__ out)
{
    int row = blockIdx.x;
    const float* xr = x + (size_t)row * EMBED_;
    float*       orow = out + (size_t)row * EMBED_;
    int tid = threadIdx.x;

    float v0 = xr[tid], v1 = xr[tid + 256], v2 = xr[tid + 512];
    float s  = v0 + v1 + v2;
    float s2 = v0 * v0 + v1 * v1 + v2 * v2;

    #pragma unroll
    for (int o = 16; o > 0; o >>= 1) {
        s  += __shfl_xor_sync(0xffffffffu, s,  o);
        s2 += __shfl_xor_sync(0xffffffffu, s2, o);
    }
    __shared__ float sm1[8], sm2[8];
    int warp = tid >> 5, lane = tid & 31;
    if (lane == 0) { sm1[warp] = s; sm2[warp] = s2; }
    __syncthreads();
    float ts = 0.f, ts2 = 0.f;
    #pragma unroll
    for (int w = 0; w < 8; w++) { ts += sm1[w]; ts2 += sm2[w]; }

    float mu  = ts * (1.0f / EMBED_);
    float var = ts2 * (1.0f / EMBED_) - mu * mu;
    float inv = rsqrtf(var + 1e-5f);

    orow[tid      ] = (v0 - mu) * inv * g[tid      ] + b[tid      ];
    orow[tid + 256] = (v1 - mu) * inv * g[tid + 256] + b[tid + 256];
    orow[tid + 512] = (v2 - mu) * inv * g[tid + 512] + b[tid + 512];
}

// ---------------------------------------------------------------------------
// SGEMM: C[M,N] = A[M,K] @ W[N,K]^T + bias + (epilogue)
// EPI: 0 = bias only, 1 = bias + residual, 2 = bias + exact GELU
// Requires M%128==0, N%128==0, K%16==0 (true for all call sites).
// 128x128 block tile, K-tile 16, 256 threads, 8x8 per-thread accumulator.
// ---------------------------------------------------------------------------
template <int EPI>
__global__ __launch_bounds__(256) void sgemm_kernel(
    const float* __restrict__ A, const float* __restrict__ W,
    const float* __restrict__ bias, const float* __restrict__ res,
    float* __restrict__ C, int M, int N, int K)
{
    __shared__ float As[16][132];
    __shared__ float Bs[16][132];

    int tid   = threadIdx.x;
    int mBase = blockIdx.y * 128;
    int nBase = blockIdx.x * 128;
    int ty = tid >> 4, tx = tid & 15;
    int rr = ty * 8, cc = tx * 8;

    float acc[8][8];
    #pragma unroll
    for (int i = 0; i < 8; i++)
        #pragma unroll
        for (int j = 0; j < 8; j++) acc[i][j] = 0.f;

    for (int k0 = 0; k0 < K; k0 += 16) {
        #pragma unroll
        for (int it = 0; it < 2; it++) {
            int flat = tid + it * 256;          // 0..511
            int m  = flat >> 2;                 // 0..127
            int kq = (flat & 3) << 2;           // 0,4,8,12
            float4 va = *(const float4*)(A + (size_t)(mBase + m) * K + k0 + kq);
            As[kq + 0][m] = va.x; As[kq + 1][m] = va.y;
            As[kq + 2][m] = va.z; As[kq + 3][m] = va.w;
            float4 vb = *(const float4*)(W + (size_t)(nBase + m) * K + k0 + kq);
            Bs[kq + 0][m] = vb.x; Bs[kq + 1][m] = vb.y;
            Bs[kq + 2][m] = vb.z; Bs[kq + 3][m] = vb.w;
        }
        __syncthreads();

        #pragma unroll
        for (int kk = 0; kk < 16; kk++) {
            float a[8], bv[8];
            *(float4*)(a)      = *(const float4*)&As[kk][rr];
            *(float4*)(a + 4)  = *(const float4*)&As[kk][rr + 4];
            *(float4*)(bv)     = *(const float4*)&Bs[kk][cc];
            *(float4*)(bv + 4) = *(const float4*)&Bs[kk][cc + 4];
            #pragma unroll
            for (int i = 0; i < 8; i++)
                #pragma unroll
                for (int j = 0; j < 8; j++)
                    acc[i][j] = fmaf(a[i], bv[j], acc[i][j]);
        }
        __syncthreads();
    }

    #pragma unroll
    for (int i = 0; i < 8; i++) {
        int row = mBase + rr + i;
        #pragma unroll
        for (int j = 0; j < 8; j += 4) {
            int col = nBase + cc + j;
            float4 v;
            v.x = acc[i][j + 0] + bias[col + 0];
            v.y = acc[i][j + 1] + bias[col + 1];
            v.z = acc[i][j + 2] + bias[col + 2];
            v.w = acc[i][j + 3] + bias[col + 3];
            if (EPI == 1) {
                const float4 r4 = *(const float4*)(res + (size_t)row * N + col);
                v.x += r4.x; v.y += r4.y; v.z += r4.z; v.w += r4.w;
            } else if (EPI == 2) {
                v.x = 0.5f * v.x * (1.0f + erff(v.x * 0.70710678118654752f));
                v.y = 0.5f * v.y * (1.0f + erff(v.y * 0.70710678118654752f));
                v.z = 0.5f * v.z * (1.0f + erff(v.z * 0.70710678118654752f));
                v.w = 0.5f * v.w * (1.0f + erff(v.w * 0.70710678118654752f));
            }
            *(float4*)(C + (size_t)row * N + col) = v;
        }
    }
}

// ---------------------------------------------------------------------------
// Flash attention (full, non-causal). grid = (N/64 q-tiles, B*HEADS).
// qkv layout: [token, s*768 + h*64 + d]. Online softmax, Br=Bc=64.
// Dynamic smem: Qt[64][68] (d-major) + Kt[64][68] (d-major) +
//               Vs[64][68] (key-major) + Ps[64][68] = 69632 B.
// ---------------------------------------------------------------------------
#define FPAD 68
#define FLASH_SMEM (4 * 64 * FPAD * 4)

__global__ __launch_bounds__(256) void flash_kernel(
    const float* __restrict__ qkv, float* __restrict__ ctx)
{
    extern __shared__ float sm[];
    float* Qt = sm;
    float* Kt = Qt + 64 * FPAD;
    float* Vs = Kt + 64 * FPAD;
    float* Ps = Vs + 64 * FPAD;

    int tid = threadIdx.x;
    int qt  = blockIdx.x;               // query tile 0..15
    int bh  = blockIdx.y;               // 0..95
    int bb  = bh / HEADS_, h = bh % HEADS_;

    const float* base = qkv + (size_t)bb * N_ * QKVW_ + h * HD_;

    // load Q tile transposed: Qt[d][q]
    #pragma unroll
    for (int p = 0; p < 16; p++) {
        int idx = p * 256 + tid;
        int row = idx >> 6, d = idx & 63;
        Qt[d * FPAD + row] = base[(size_t)(qt * 64 + row) * QKVW_ + d];
    }

    int ty = tid >> 4, tx = tid & 15;
    int rq = ty * 4, cq = tx * 4;

    float m_i[4], l_i[4], acc[4][4];
    #pragma unroll
    for (int i = 0; i < 4; i++) {
        m_i[i] = -1e30f; l_i[i] = 0.f;
        #pragma unroll
        for (int j = 0; j < 4; j++) acc[i][j] = 0.f;
    }

    for (int t = 0; t < 16; t++) {
        __syncthreads();   // prior-iter P/V consumption done; Q visible on t==0
        #pragma unroll
        for (int p = 0; p < 16; p++) {
            int idx = p * 256 + tid;
            int row = idx >> 6, d = idx & 63;
            size_t gofs = (size_t)(t * 64 + row) * QKVW_ + d;
            Kt[d * FPAD + row] = base[gofs + EMBED_];       // K, d-major
            Vs[row * FPAD + d] = base[gofs + 2 * EMBED_];   // V, key-major
        }
        __syncthreads();

        // S = Q K^T (4x4 per thread)
        float s[4][4];
        #pragma unroll
        for (int i = 0; i < 4; i++)
            #pragma unroll
            for (int j = 0; j < 4; j++) s[i][j] = 0.f;

        #pragma unroll 16
        for (int d = 0; d < 64; d++) {
            float4 qa = *(const float4*)&Qt[d * FPAD + rq];
            float4 kb = *(const float4*)&Kt[d * FPAD + cq];
            float aq[4] = {qa.x, qa.y, qa.z, qa.w};
            float bk[4] = {kb.x, kb.y, kb.z, kb.w};
            #pragma unroll
            for (int i = 0; i < 4; i++)
                #pragma unroll
                for (int j = 0; j < 4; j++)
                    s[i][j] = fmaf(aq[i], bk[j], s[i][j]);
        }

        // online softmax update
        #pragma unroll
        for (int i = 0; i < 4; i++) {
            #pragma unroll
            for (int j = 0; j < 4; j++) s[i][j] *= 0.125f;  // HEAD_DIM^-0.5

            float mx = fmaxf(fmaxf(s[i][0], s[i][1]), fmaxf(s[i][2], s[i][3]));
            #pragma unroll
            for (int o = 1; o < 16; o <<= 1)
                mx = fmaxf(mx, __shfl_xor_sync(0xffffffffu, mx, o));
            float mnew = fmaxf(m_i[i], mx);
            float alpha = expf(m_i[i] - mnew);
            m_i[i] = mnew;

            float rs = 0.f;
            #pragma unroll
            for (int j = 0; j < 4; j++) {
                s[i][j] = expf(s[i][j] - mnew);
                rs += s[i][j];
            }
            #pragma unroll
            for (int o = 1; o < 16; o <<= 1)
                rs += __shfl_xor_sync(0xffffffffu, rs, o);

            l_i[i] = l_i[i] * alpha + rs;
            #pragma unroll
            for (int j = 0; j < 4; j++) acc[i][j] *= alpha;

            *(float4*)&Ps[(rq + i) * FPAD + cq] =
                make_float4(s[i][0], s[i][1], s[i][2], s[i][3]);
        }
        __syncthreads();

        // O += P @ V
        #pragma unroll 16
        for (int k = 0; k < 64; k++) {
            float4 vv = *(const float4*)&Vs[k * FPAD + cq];
            #pragma unroll
            for (int i = 0; i < 4; i++) {
                float pa = Ps[(rq + i) * FPAD + k];
                acc[i][0] = fmaf(pa, vv.x, acc[i][0]);
                acc[i][1] = fmaf(pa, vv.y, acc[i][1]);
                acc[i][2] = fmaf(pa, vv.z, acc[i][2]);
                acc[i][3] = fmaf(pa, vv.w, acc[i][3]);
            }
        }
    }

    // write ctx[token, h*64 + d]
    #pragma unroll
    for (int i = 0; i < 4; i++) {
        int token = bb * N_ + qt * 64 + rq + i;
        float inv = 1.0f / l_i[i];
        float4 o = make_float4(acc[i][0] * inv, acc[i][1] * inv,
                               acc[i][2] * inv, acc[i][3] * inv);
        *(float4*)(ctx + (size_t)token * EMBED_ + h * HD_ + cq) = o;
    }
}

// ---------------------------------------------------------------------------
// launch
// ---------------------------------------------------------------------------
extern "C" void kernel_launch(void* const* d_in, const int* in_sizes, int n_in,
                              void* d_out, int out_size)
{
    const float* x      = (const float*)d_in[0];
    const float* ln1_g  = (const float*)d_in[1];
    const float* ln1_b  = (const float*)d_in[2];
    const float* qkv_w  = (const float*)d_in[3];
    const float* qkv_b  = (const float*)d_in[4];
    const float* proj_w = (const float*)d_in[5];
    const float* proj_b = (const float*)d_in[6];
    const float* ln2_g  = (const float*)d_in[7];
    const float* ln2_b  = (const float*)d_in[8];
    const float* fc1_w  = (const float*)d_in[9];
    const float* fc1_b  = (const float*)d_in[10];
    const float* fc2_w  = (const float*)d_in[11];
    const float* fc2_b  = (const float*)d_in[12];
    float* out = (float*)d_out;

    float *h, *qkv, *ctx, *x1, *h2, *ffn;
    cudaGetSymbolAddress((void**)&h,   g_h);
    cudaGetSymbolAddress((void**)&qkv, g_qkv);
    cudaGetSymbolAddress((void**)&ctx, g_ctx);
    cudaGetSymbolAddress((void**)&x1,  g_x1);
    cudaGetSymbolAddress((void**)&h2,  g_h2);
    cudaGetSymbolAddress((void**)&ffn, g_ffn);

    cudaFuncSetAttribute(flash_kernel,
                         cudaFuncAttributeMaxDynamicSharedMemorySize, FLASH_SMEM);

    // ln1
    ln_kernel<<<TOKENS_, 256>>>(x, ln1_g, ln1_b, h);
    // qkv = h @ qkv_w^T + b
    sgemm_kernel<0><<<dim3(QKVW_ / 128, TOKENS_ / 128), 256>>>(
        h, qkv_w, qkv_b, nullptr, qkv, TOKENS_, QKVW_, EMBED_);
    // attention
    flash_kernel<<<dim3(N_ / 64, B_ * HEADS_), 256, FLASH_SMEM>>>(qkv, ctx);
    // x1 = x + ctx @ proj_w^T + b
    sgemm_kernel<1><<<dim3(EMBED_ / 128, TOKENS_ / 128), 256>>>(
        ctx, proj_w, proj_b, x, x1, TOKENS_, EMBED_, EMBED_);
    // ln2
    ln_kernel<<<TOKENS_, 256>>>(x1, ln2_g, ln2_b, h2);
    // ffn = gelu(h2 @ fc1_w^T + b)
    sgemm_kernel<2><<<dim3(HIDDEN_ / 128, TOKENS_ / 128), 256>>>(
        h2, fc1_w, fc1_b, nullptr, ffn, TOKENS_, HIDDEN_, EMBED_);
    // out = x1 + ffn @ fc2_w^T + b
    sgemm_kernel<1><<<dim3(EMBED_ / 128, TOKENS_ / 128), 256>>>(
        ffn, fc2_w, fc2_b, x1, out, TOKENS_, EMBED_, HIDDEN_);
}

// round 5
// speedup vs baseline: 2.1072x; 2.1072x over previous
#include <cuda_runtime.h>
#include <cuda_bf16.h>
#include <math.h>
#include <stdint.h>

// ---------------------------------------------------------------------------
// TransformerBlock: B=8, N=1024, EMBED=768, HEADS=12, HEAD_DIM=64, HIDDEN=3072
// GEMMs: mma.sync.m16n8k8 tf32 (family-portable tensor core path; tcgen05 is
// rejected by the harness's sm_103 family target). fp32 accumulate.
// Operands pre-rounded to tf32 (cvt.rna) outside the GEMM mainloop.
// Attention: fp32 flash kernel. LN: fp32 warp-reduce kernel.
// ---------------------------------------------------------------------------

#define B_      8
#define N_      1024
#define EMBED_  768
#define HEADS_  12
#define HD_     64
#define HIDDEN_ 3072
#define TOKENS_ (B_ * N_)          // 8192
#define QKVW_   (3 * EMBED_)       // 2304

// ---- scratch (static device globals: allocation-free) ----
__device__ float g_h   [TOKENS_ * EMBED_];
__device__ float g_qkv [TOKENS_ * QKVW_];
__device__ float g_ctx [TOKENS_ * EMBED_];
__device__ float g_x1  [TOKENS_ * EMBED_];
__device__ float g_h2  [TOKENS_ * EMBED_];
__device__ float g_ffn [TOKENS_ * HIDDEN_];
// tf32-rounded weight copies
__device__ float g_wq  [QKVW_  * EMBED_];
__device__ float g_wp  [EMBED_ * EMBED_];
__device__ float g_w1  [HIDDEN_ * EMBED_];
__device__ float g_w2  [EMBED_ * HIDDEN_];

// ---------------------------------------------------------------------------
// helpers
// ---------------------------------------------------------------------------
__device__ __forceinline__ float tf32r(float x) {
    uint32_t u;
    asm("cvt.rna.tf32.f32 %0, %1;" : "=r"(u) : "f"(x));
    return __uint_as_float(u);
}
__device__ __forceinline__ uint32_t smem_u32(const void* p) {
    uint32_t a;
    asm("{ .reg .u64 t; cvta.to.shared.u64 t, %1; cvt.u32.u64 %0, t; }"
        : "=r"(a) : "l"(p));
    return a;
}
#define CP_ASYNC16(dst, src) \
    asm volatile("cp.async.cg.shared.global [%0], [%1], 16;" \
                 :: "r"(dst), "l"(src) : "memory")
#define CP_COMMIT()  asm volatile("cp.async.commit_group;" ::: "memory")
#define CP_WAIT2()   asm volatile("cp.async.wait_group 2;" ::: "memory")

__device__ __forceinline__ void mma_tf32(float* d, const uint32_t* a,
                                         const uint32_t* b) {
    asm volatile(
        "mma.sync.aligned.m16n8k8.row.col.f32.tf32.tf32.f32 "
        "{%0,%1,%2,%3}, {%4,%5,%6,%7}, {%8,%9}, {%0,%1,%2,%3};"
        : "+f"(d[0]), "+f"(d[1]), "+f"(d[2]), "+f"(d[3])
        : "r"(a[0]), "r"(a[1]), "r"(a[2]), "r"(a[3]), "r"(b[0]), "r"(b[1]));
}

// ---------------------------------------------------------------------------
// tf32 rounding copy kernel (weights)
// ---------------------------------------------------------------------------
__global__ __launch_bounds__(256) void round_tf32_kernel(
    const float* __restrict__ in, float* __restrict__ out, int n4)
{
    int i = blockIdx.x * blockDim.x + threadIdx.x;
    if (i < n4) {
        float4 v = ((const float4*)in)[i];
        v.x = tf32r(v.x); v.y = tf32r(v.y); v.z = tf32r(v.z); v.w = tf32r(v.w);
        ((float4*)out)[i] = v;
    }
}

// ---------------------------------------------------------------------------
// mma.sync tf32 GEMM: C[M,Nn] = A[M,K] @ W[Nn,K]^T + bias (+res / +gelu)
// EPI: 0 = bias, 1 = bias + residual, 2 = bias + exact GELU (tf32-rounded out)
// CTA 128x128, BK=16, 256 thr / 8 warps (2Mx4N, 64x32 per warp), 4 stages.
// smem row stride 20 floats -> conflict-free fragment LDS.
// ---------------------------------------------------------------------------
#define BK          16
#define ROWSTRIDE   20
#define MAT_FLOATS  (128 * ROWSTRIDE)          // 2560
#define STAGE_FLOATS (2 * MAT_FLOATS)          // A + W
#define STAGES      4
#define GEMM_DSMEM  (STAGES * STAGE_FLOATS * 4) // 81920 B

template <int EPI>
__global__ __launch_bounds__(256, 2) void mma_gemm(
    const float* __restrict__ A, const float* __restrict__ W,
    const float* __restrict__ bias, const float* __restrict__ res,
    float* __restrict__ C, int M, int Nn, int K)
{
    extern __shared__ float smf[];

    const int tid  = threadIdx.x;
    const int wid  = tid >> 5, lane = tid & 31;
    const int mBase = blockIdx.y * 128;
    const int nBase = blockIdx.x * 128;
    const int warp_m = wid & 1;        // 0..1
    const int warp_n = wid >> 1;       // 0..3
    const int g = lane >> 2;           // 0..7
    const int q = lane & 3;            // 0..3

    const uint32_t sm_base = smem_u32(smf);

    // per-thread cp.async mapping: 2 float4 per matrix per ktile
    // flat = tid + it*256 in [0,512): m = flat>>2, kq = (flat&3)*4
    int mL[2], kqL[2];
    #pragma unroll
    for (int it = 0; it < 2; it++) {
        int flat = tid + it * 256;
        mL[it]  = flat >> 2;
        kqL[it] = (flat & 3) << 2;
    }
    const float* Arow = A + (size_t)mBase * K;
    const float* Wrow = W + (size_t)nBase * K;

    const int nK = K / BK;

    // accumulators: 4 m-frags x 4 n-frags x 4 regs
    float acc[4][4][4];
    #pragma unroll
    for (int i = 0; i < 4; i++)
        #pragma unroll
        for (int j = 0; j < 4; j++)
            #pragma unroll
            for (int r = 0; r < 4; r++) acc[i][j][r] = 0.f;

    // ---- prologue: issue 3 stages ----
    #pragma unroll
    for (int t = 0; t < 3; t++) {
        uint32_t sb = sm_base + (uint32_t)(t * STAGE_FLOATS) * 4u;
        int k0 = t * BK;
        #pragma unroll
        for (int it = 0; it < 2; it++) {
            uint32_t doff = (uint32_t)(mL[it] * ROWSTRIDE + kqL[it]) * 4u;
            CP_ASYNC16(sb + doff,              Arow + (size_t)mL[it] * K + k0 + kqL[it]);
            CP_ASYNC16(sb + MAT_FLOATS*4u + doff, Wrow + (size_t)mL[it] * K + k0 + kqL[it]);
        }
        CP_COMMIT();
    }

    // fragment row/col bases in smem
    int rA[4], cB[4];
    #pragma unroll
    for (int i = 0; i < 4; i++) rA[i] = (warp_m * 64 + i * 16 + g) * ROWSTRIDE;
    #pragma unroll
    for (int j = 0; j < 4; j++) cB[j] = (warp_n * 32 + j * 8 + g) * ROWSTRIDE;

    // ---- mainloop ----
    #pragma unroll 1
    for (int kt = 0; kt < nK; kt++) {
        CP_WAIT2();
        __syncthreads();

        const float* As = smf + (kt & 3) * STAGE_FLOATS;
        const float* Ws = As + MAT_FLOATS;
        const uint32_t* Au = (const uint32_t*)As;
        const uint32_t* Wu = (const uint32_t*)Ws;

        #pragma unroll
        for (int ks = 0; ks < 2; ks++) {
            int k = ks * 8 + q;
            uint32_t a[4][4], b[4][2];
            #pragma unroll
            for (int i = 0; i < 4; i++) {
                a[i][0] = Au[rA[i] + k];
                a[i][1] = Au[rA[i] + 8 * ROWSTRIDE + k];
                a[i][2] = Au[rA[i] + k + 4];
                a[i][3] = Au[rA[i] + 8 * ROWSTRIDE + k + 4];
            }
            #pragma unroll
            for (int j = 0; j < 4; j++) {
                b[j][0] = Wu[cB[j] + k];
                b[j][1] = Wu[cB[j] + k + 4];
            }
            #pragma unroll
            for (int i = 0; i < 4; i++)
                #pragma unroll
                for (int j = 0; j < 4; j++)
                    mma_tf32(acc[i][j], a[i], b[j]);
        }
        __syncthreads();

        int ft = kt + 3;
        if (ft < nK) {
            uint32_t sb = sm_base + (uint32_t)((ft & 3) * STAGE_FLOATS) * 4u;
            int k0 = ft * BK;
            #pragma unroll
            for (int it = 0; it < 2; it++) {
                uint32_t doff = (uint32_t)(mL[it] * ROWSTRIDE + kqL[it]) * 4u;
                CP_ASYNC16(sb + doff,              Arow + (size_t)mL[it] * K + k0 + kqL[it]);
                CP_ASYNC16(sb + MAT_FLOATS*4u + doff, Wrow + (size_t)mL[it] * K + k0 + kqL[it]);
            }
        }
        CP_COMMIT();
    }

    // ---- epilogue ----
    #pragma unroll
    for (int i = 0; i < 4; i++) {
        int row0 = mBase + warp_m * 64 + i * 16 + g;
        #pragma unroll
        for (int j = 0; j < 4; j++) {
            int col = nBase + warp_n * 32 + j * 8 + q * 2;
            float bx = bias[col], by = bias[col + 1];

            #pragma unroll
            for (int half = 0; half < 2; half++) {
                int row = row0 + half * 8;
                float vx = acc[i][j][half * 2 + 0] + bx;
                float vy = acc[i][j][half * 2 + 1] + by;
                if (EPI == 1) {
                    float2 r2 = *(const float2*)(res + (size_t)row * Nn + col);
                    vx += r2.x; vy += r2.y;
                } else if (EPI == 2) {
                    vx = 0.5f * vx * (1.0f + erff(vx * 0.70710678118654752f));
                    vy = 0.5f * vy * (1.0f + erff(vy * 0.70710678118654752f));
                    vx = tf32r(vx);   // feeds fc2 GEMM
                    vy = tf32r(vy);
                }
                float2 o; o.x = vx; o.y = vy;
                *(float2*)(C + (size_t)row * Nn + col) = o;
            }
        }
    }
}

// ---------------------------------------------------------------------------
// LayerNorm: one block per row of 768 (output tf32-rounded: feeds GEMMs)
// ---------------------------------------------------------------------------
__global__ __launch_bounds__(256) void ln_kernel(
    const float* __restrict__ x, const float* __restrict__ g,
    const float* __restrict__ b, float* __restrict__ out)
{
    int row = blockIdx.x;
    const float* xr = x + (size_t)row * EMBED_;
    float* orow = out + (size_t)row * EMBED_;
    int tid = threadIdx.x;

    float v0 = xr[tid], v1 = xr[tid + 256], v2 = xr[tid + 512];
    float s  = v0 + v1 + v2;
    float s2 = v0 * v0 + v1 * v1 + v2 * v2;

    #pragma unroll
    for (int o = 16; o > 0; o >>= 1) {
        s  += __shfl_xor_sync(0xffffffffu, s,  o);
        s2 += __shfl_xor_sync(0xffffffffu, s2, o);
    }
    __shared__ float sm1[8], sm2[8];
    int warp = tid >> 5, lane = tid & 31;
    if (lane == 0) { sm1[warp] = s; sm2[warp] = s2; }
    __syncthreads();
    float ts = 0.f, ts2 = 0.f;
    #pragma unroll
    for (int w = 0; w < 8; w++) { ts += sm1[w]; ts2 += sm2[w]; }

    float mu  = ts * (1.0f / EMBED_);
    float var = ts2 * (1.0f / EMBED_) - mu * mu;
    float inv = rsqrtf(var + 1e-5f);

    orow[tid      ] = tf32r((v0 - mu) * inv * g[tid      ] + b[tid      ]);
    orow[tid + 256] = tf32r((v1 - mu) * inv * g[tid + 256] + b[tid + 256]);
    orow[tid + 512] = tf32r((v2 - mu) * inv * g[tid + 512] + b[tid + 512]);
}

// ---------------------------------------------------------------------------
// Flash attention (full, non-causal). grid = (N/64 q-tiles, B*HEADS).
// ctx output tf32-rounded (feeds proj GEMM).
// ---------------------------------------------------------------------------
#define FPAD 68
#define FLASH_SMEM (4 * 64 * FPAD * 4)

__global__ __launch_bounds__(256) void flash_kernel(
    const float* __restrict__ qkv, float* __restrict__ ctx)
{
    extern __shared__ float sm[];
    float* Qt = sm;
    float* Kt = Qt + 64 * FPAD;
    float* Vs = Kt + 64 * FPAD;
    float* Ps = Vs + 64 * FPAD;

    int tid = threadIdx.x;
    int qt  = blockIdx.x;
    int bh  = blockIdx.y;
    int bb  = bh / HEADS_, h = bh % HEADS_;

    const float* base = qkv + (size_t)bb * N_ * QKVW_ + h * HD_;

    #pragma unroll
    for (int p = 0; p < 16; p++) {
        int idx = p * 256 + tid;
        int row = idx >> 6, d = idx & 63;
        Qt[d * FPAD + row] = base[(size_t)(qt * 64 + row) * QKVW_ + d];
    }

    int ty = tid >> 4, tx = tid & 15;
    int rq = ty * 4, cq = tx * 4;

    float m_i[4], l_i[4], acc[4][4];
    #pragma unroll
    for (int i = 0; i < 4; i++) {
        m_i[i] = -1e30f; l_i[i] = 0.f;
        #pragma unroll
        for (int j = 0; j < 4; j++) acc[i][j] = 0.f;
    }

    for (int t = 0; t < 16; t++) {
        __syncthreads();
        #pragma unroll
        for (int p = 0; p < 16; p++) {
            int idx = p * 256 + tid;
            int row = idx >> 6, d = idx & 63;
            size_t gofs = (size_t)(t * 64 + row) * QKVW_ + d;
            Kt[d * FPAD + row] = base[gofs + EMBED_];
            Vs[row * FPAD + d] = base[gofs + 2 * EMBED_];
        }
        __syncthreads();

        float s[4][4];
        #pragma unroll
        for (int i = 0; i < 4; i++)
            #pragma unroll
            for (int j = 0; j < 4; j++) s[i][j] = 0.f;

        #pragma unroll 16
        for (int d = 0; d < 64; d++) {
            float4 qa = *(const float4*)&Qt[d * FPAD + rq];
            float4 kb = *(const float4*)&Kt[d * FPAD + cq];
            float aq[4] = {qa.x, qa.y, qa.z, qa.w};
            float bk[4] = {kb.x, kb.y, kb.z, kb.w};
            #pragma unroll
            for (int i = 0; i < 4; i++)
                #pragma unroll
                for (int j = 0; j < 4; j++)
                    s[i][j] = fmaf(aq[i], bk[j], s[i][j]);
        }

        #pragma unroll
        for (int i = 0; i < 4; i++) {
            #pragma unroll
            for (int j = 0; j < 4; j++) s[i][j] *= 0.125f;

            float mx = fmaxf(fmaxf(s[i][0], s[i][1]), fmaxf(s[i][2], s[i][3]));
            #pragma unroll
            for (int o = 1; o < 16; o <<= 1)
                mx = fmaxf(mx, __shfl_xor_sync(0xffffffffu, mx, o));
            float mnew = fmaxf(m_i[i], mx);
            float alpha = expf(m_i[i] - mnew);
            m_i[i] = mnew;

            float rs = 0.f;
            #pragma unroll
            for (int j = 0; j < 4; j++) {
                s[i][j] = expf(s[i][j] - mnew);
                rs += s[i][j];
            }
            #pragma unroll
            for (int o = 1; o < 16; o <<= 1)
                rs += __shfl_xor_sync(0xffffffffu, rs, o);

            l_i[i] = l_i[i] * alpha + rs;
            #pragma unroll
            for (int j = 0; j < 4; j++) acc[i][j] *= alpha;

            *(float4*)&Ps[(rq + i) * FPAD + cq] =
                make_float4(s[i][0], s[i][1], s[i][2], s[i][3]);
        }
        __syncthreads();

        #pragma unroll 16
        for (int k = 0; k < 64; k++) {
            float4 vv = *(const float4*)&Vs[k * FPAD + cq];
            #pragma unroll
            for (int i = 0; i < 4; i++) {
                float pa = Ps[(rq + i) * FPAD + k];
                acc[i][0] = fmaf(pa, vv.x, acc[i][0]);
                acc[i][1] = fmaf(pa, vv.y, acc[i][1]);
                acc[i][2] = fmaf(pa, vv.z, acc[i][2]);
                acc[i][3] = fmaf(pa, vv.w, acc[i][3]);
            }
        }
    }

    #pragma unroll
    for (int i = 0; i < 4; i++) {
        int token = bb * N_ + qt * 64 + rq + i;
        float inv = 1.0f / l_i[i];
        float4 o = make_float4(tf32r(acc[i][0] * inv), tf32r(acc[i][1] * inv),
                               tf32r(acc[i][2] * inv), tf32r(acc[i][3] * inv));
        *(float4*)(ctx + (size_t)token * EMBED_ + h * HD_ + cq) = o;
    }
}

// ---------------------------------------------------------------------------
// launch
// ---------------------------------------------------------------------------
extern "C" void kernel_launch(void* const* d_in, const int* in_sizes, int n_in,
                              void* d_out, int out_size)
{
    const float* x      = (const float*)d_in[0];
    const float* ln1_g  = (const float*)d_in[1];
    const float* ln1_b  = (const float*)d_in[2];
    const float* qkv_w  = (const float*)d_in[3];
    const float* qkv_b  = (const float*)d_in[4];
    const float* proj_w = (const float*)d_in[5];
    const float* proj_b = (const float*)d_in[6];
    const float* ln2_g  = (const float*)d_in[7];
    const float* ln2_b  = (const float*)d_in[8];
    const float* fc1_w  = (const float*)d_in[9];
    const float* fc1_b  = (const float*)d_in[10];
    const float* fc2_w  = (const float*)d_in[11];
    const float* fc2_b  = (const float*)d_in[12];
    float* out = (float*)d_out;

    float *h, *qkv, *ctx, *x1, *h2, *ffn, *wq, *wp, *w1, *w2;
    cudaGetSymbolAddress((void**)&h,   g_h);
    cudaGetSymbolAddress((void**)&qkv, g_qkv);
    cudaGetSymbolAddress((void**)&ctx, g_ctx);
    cudaGetSymbolAddress((void**)&x1,  g_x1);
    cudaGetSymbolAddress((void**)&h2,  g_h2);
    cudaGetSymbolAddress((void**)&ffn, g_ffn);
    cudaGetSymbolAddress((void**)&wq,  g_wq);
    cudaGetSymbolAddress((void**)&wp,  g_wp);
    cudaGetSymbolAddress((void**)&w1,  g_w1);
    cudaGetSymbolAddress((void**)&w2,  g_w2);

    cudaFuncSetAttribute(flash_kernel,
                         cudaFuncAttributeMaxDynamicSharedMemorySize, FLASH_SMEM);
    cudaFuncSetAttribute(mma_gemm<0>,
                         cudaFuncAttributeMaxDynamicSharedMemorySize, GEMM_DSMEM);
    cudaFuncSetAttribute(mma_gemm<1>,
                         cudaFuncAttributeMaxDynamicSharedMemorySize, GEMM_DSMEM);
    cudaFuncSetAttribute(mma_gemm<2>,
                         cudaFuncAttributeMaxDynamicSharedMemorySize, GEMM_DSMEM);

    // tf32-round the weights into scratch
    {
        int n4;
        n4 = QKVW_ * EMBED_ / 4;
        round_tf32_kernel<<<(n4 + 255) / 256, 256>>>(qkv_w, wq, n4);
        n4 = EMBED_ * EMBED_ / 4;
        round_tf32_kernel<<<(n4 + 255) / 256, 256>>>(proj_w, wp, n4);
        n4 = HIDDEN_ * EMBED_ / 4;
        round_tf32_kernel<<<(n4 + 255) / 256, 256>>>(fc1_w, w1, n4);
        n4 = EMBED_ * HIDDEN_ / 4;
        round_tf32_kernel<<<(n4 + 255) / 256, 256>>>(fc2_w, w2, n4);
    }

    // ln1
    ln_kernel<<<TOKENS_, 256>>>(x, ln1_g, ln1_b, h);
    // qkv = h @ qkv_w^T + b
    mma_gemm<0><<<dim3(QKVW_ / 128, TOKENS_ / 128), 256, GEMM_DSMEM>>>(
        h, wq, qkv_b, nullptr, qkv, TOKENS_, QKVW_, EMBED_);
    // attention
    flash_kernel<<<dim3(N_ / 64, B_ * HEADS_), 256, FLASH_SMEM>>>(qkv, ctx);
    // x1 = x + ctx @ proj_w^T + b
    mma_gemm<1><<<dim3(EMBED_ / 128, TOKENS_ / 128), 256, GEMM_DSMEM>>>(
        ctx, wp, proj_b, x, x1, TOKENS_, EMBED_, EMBED_);
    // ln2
    ln_kernel<<<TOKENS_, 256>>>(x1, ln2_g, ln2_b, h2);
    // ffn = gelu(h2 @ fc1_w^T + b)   (tf32-rounded store)
    mma_gemm<2><<<dim3(HIDDEN_ / 128, TOKENS_ / 128), 256, GEMM_DSMEM>>>(
        h2, w1, fc1_b, nullptr, ffn, TOKENS_, HIDDEN_, EMBED_);
    // out = x1 + ffn @ fc2_w^T + b
    mma_gemm<1><<<dim3(EMBED_ / 128, TOKENS_ / 128), 256, GEMM_DSMEM>>>(
        ffn, w2, fc2_b, x1, out, TOKENS_, EMBED_, HIDDEN_);
}